// round 5
// baseline (speedup 1.0000x reference)
#include <cuda_runtime.h>
#include <cuda_fp16.h>

#define N_NODES 100000
#define N_EDGES 1250000
#define NGRAPH  256
#define HID     64
#define IN_DIM  7

#define SCAN_E  1024
#define SCAN_B  ((N_NODES + SCAN_E - 1) / SCAN_E)   // 98

// ---------------- scratch (device globals; no allocation allowed) ----------
__device__ float g_dinv[N_NODES];
__device__ int   g_deg[N_NODES];
__device__ int   g_rowptr[N_NODES + 1];
__device__ int   g_cursor[N_NODES];
__device__ int   g_csr[N_EDGES];
__device__ int   g_partials[SCAN_B];
__device__ __align__(16) __half g_bufH[N_NODES * HID];  // fp16 gathered features g
__device__ __align__(16) float  g_bufF[N_NODES * HID];  // fp32 hidden H
__device__ __align__(16) float  g_x7[N_NODES * IN_DIM];
__device__ __align__(16) float  g_a7[N_NODES * IN_DIM];

// ---------------- setup kernels -------------------------------------------
__global__ void k_zero() {
    int i = blockIdx.x * blockDim.x + threadIdx.x;
    if (i < N_NODES) g_deg[i] = 0;
}

__global__ void k_deg(const int* __restrict__ ei) {
    int e = blockIdx.x * blockDim.x + threadIdx.x;
    if (e < N_EDGES) atomicAdd(&g_deg[ei[N_EDGES + e]], 1);
}

// exclusive scan of g_deg -> g_rowptr (block-local), raw block sums -> g_partials
__global__ void k_scan1() {
    __shared__ int wraw[8], wscan[8];
    int t = threadIdx.x, b = blockIdx.x;
    int base = b * SCAN_E + t * 4;
    int v0 = 0, v1 = 0, v2 = 0, v3 = 0;
    if (base + 0 < N_NODES) v0 = g_deg[base + 0];
    if (base + 1 < N_NODES) v1 = g_deg[base + 1];
    if (base + 2 < N_NODES) v2 = g_deg[base + 2];
    if (base + 3 < N_NODES) v3 = g_deg[base + 3];
    int ts = v0 + v1 + v2 + v3;
    int lane = t & 31, wid = t >> 5;
    int inc = ts;
    #pragma unroll
    for (int o = 1; o < 32; o <<= 1) {
        int y = __shfl_up_sync(0xffffffffu, inc, o);
        if (lane >= o) inc += y;
    }
    if (lane == 31) wraw[wid] = inc;
    __syncthreads();
    if (t < 8) {
        int w = wraw[t];
        #pragma unroll
        for (int o = 1; o < 8; o <<= 1) {
            int y = __shfl_up_sync(0xffu, w, o);
            if (t >= o) w += y;
        }
        wscan[t] = w;
    }
    __syncthreads();
    int ex = (wid ? wscan[wid - 1] : 0) + (inc - ts);
    if (base + 0 < N_NODES) g_rowptr[base + 0] = ex;  ex += v0;
    if (base + 1 < N_NODES) g_rowptr[base + 1] = ex;  ex += v1;
    if (base + 2 < N_NODES) g_rowptr[base + 2] = ex;  ex += v2;
    if (base + 3 < N_NODES) g_rowptr[base + 3] = ex;
    if (t == 0) g_partials[b] = wscan[7];
}

// finalize rowptr (each block sums its prefix of raw partials), cursor, dinv
__global__ void __launch_bounds__(256) k_scan3() {
    __shared__ int sprefix;
    int b = blockIdx.x;
    int p = (b * 256) / SCAN_E;           // partial index for this block (b/4)
    if (threadIdx.x < 32) {
        int s = 0;
        for (int j = threadIdx.x; j < p; j += 32) s += g_partials[j];
        #pragma unroll
        for (int o = 16; o; o >>= 1) s += __shfl_down_sync(0xffffffffu, s, o);
        if (threadIdx.x == 0) sprefix = s;
    }
    __syncthreads();
    int i = b * 256 + threadIdx.x;
    if (i < N_NODES) {
        int r = g_rowptr[i] + sprefix;
        g_rowptr[i] = r;
        g_cursor[i] = r;
        g_dinv[i] = rsqrtf((float)(g_deg[i] + 1));   // +1 self-loop
    }
    if (i == 0) {}
    if (b == 0 && threadIdx.x == 0) g_rowptr[N_NODES] = N_EDGES;
}

__global__ void k_scatter(const int* __restrict__ ei) {
    int e = blockIdx.x * blockDim.x + threadIdx.x;
    if (e < N_EDGES) {
        int d = ei[N_EDGES + e];
        int p = atomicAdd(&g_cursor[d], 1);
        g_csr[p] = ei[e];
    }
}

// ---------------- layer 1 (aggregate 7-dim x first, then GEMM) -------------
__global__ void k_gx(const float* __restrict__ x) {
    int i = blockIdx.x * blockDim.x + threadIdx.x;
    if (i < N_NODES * IN_DIM) g_x7[i] = x[i] * g_dinv[i / IN_DIM];
}

// a7[v] = dinv[v] * (x7[v] + sum_{CSR[v]} x7[u])
__global__ void __launch_bounds__(256) k_agg7() {
    int w = (blockIdx.x * blockDim.x + threadIdx.x) >> 5;
    if (w >= N_NODES) return;
    int lane = threadIdx.x & 31;
    int grp = lane / IN_DIM, dim = lane % IN_DIM;     // grp 0..3 active, 4 idle
    float acc = 0.f;
    if (grp == 0) acc = g_x7[w * IN_DIM + dim];       // self term
    if (grp < 4) {
        int beg = g_rowptr[w], end = g_rowptr[w + 1];
        for (int e = beg + grp; e < end; e += 4) {
            int u = g_csr[e];
            acc += g_x7[u * IN_DIM + dim];
        }
    }
    __syncwarp();
    acc += __shfl_down_sync(0xffffffffu, acc, 14);
    acc += __shfl_down_sync(0xffffffffu, acc, 7);
    if (lane < IN_DIM) g_a7[w * IN_DIM + lane] = acc * g_dinv[w];
}

// H1 = relu(a7 @ W1 + b1)  -> bufF (fp32)
__global__ void k_h1(const float* __restrict__ W1, const float* __restrict__ b1) {
    __shared__ float sW[IN_DIM * HID];
    int t = threadIdx.x;
    for (int i = t; i < IN_DIM * HID; i += 256) sW[i] = W1[i];
    __syncthreads();
    int w = blockIdx.x * 8 + (t >> 5);
    if (w >= N_NODES) return;
    int lane = t & 31;
    float xv = (lane < IN_DIM) ? g_a7[w * IN_DIM + lane] : 0.f;
    float a0 = b1[lane], a1 = b1[32 + lane];
    #pragma unroll
    for (int k = 0; k < IN_DIM; k++) {
        float xk = __shfl_sync(0xffffffffu, xv, k);
        a0 += xk * sW[k * HID + lane];
        a1 += xk * sW[k * HID + 32 + lane];
    }
    g_bufF[w * HID + lane]      = fmaxf(a0, 0.f);
    g_bufF[w * HID + 32 + lane] = fmaxf(a1, 0.f);
}

// ---------------- 64-dim layers --------------------------------------------
// GEMM tile: bufH = (half) dinv[v] * (bufF[v] @ W), 64 nodes/block
__global__ void __launch_bounds__(256) k_xw64(const float* __restrict__ W) {
    __shared__ __align__(16) float sA[64][68];  // sA[k][m]
    __shared__ __align__(16) float sW[64][68];  // sW[k][n]
    int t = threadIdx.x;
    int nb = blockIdx.x * 64;
    for (int i = t; i < 4096; i += 256) {
        int k = i >> 6, n = i & 63;
        sW[k][n] = W[i];
        int m = i >> 6, kk = i & 63;
        int node = nb + m;
        sA[kk][m] = (node < N_NODES) ? g_bufF[node * HID + kk] : 0.f;
    }
    __syncthreads();
    int tx = t & 15, ty = t >> 4;
    float acc[4][4] = {};
    #pragma unroll
    for (int k = 0; k < 64; k++) {
        float4 a = *(const float4*)&sA[k][ty * 4];
        float4 wv = *(const float4*)&sW[k][tx * 4];
        acc[0][0] += a.x * wv.x; acc[0][1] += a.x * wv.y; acc[0][2] += a.x * wv.z; acc[0][3] += a.x * wv.w;
        acc[1][0] += a.y * wv.x; acc[1][1] += a.y * wv.y; acc[1][2] += a.y * wv.z; acc[1][3] += a.y * wv.w;
        acc[2][0] += a.z * wv.x; acc[2][1] += a.z * wv.y; acc[2][2] += a.z * wv.z; acc[2][3] += a.z * wv.w;
        acc[3][0] += a.w * wv.x; acc[3][1] += a.w * wv.y; acc[3][2] += a.w * wv.z; acc[3][3] += a.w * wv.w;
    }
    #pragma unroll
    for (int m = 0; m < 4; m++) {
        int node = nb + ty * 4 + m;
        if (node < N_NODES) {
            float s = g_dinv[node];
            __half2 h0 = __floats2half2_rn(acc[m][0] * s, acc[m][1] * s);
            __half2 h1 = __floats2half2_rn(acc[m][2] * s, acc[m][3] * s);
            uint2 pk;
            pk.x = *(const unsigned int*)&h0;
            pk.y = *(const unsigned int*)&h1;
            *(uint2*)&g_bufH[node * HID + tx * 4] = pk;
        }
    }
}

// aggregation (fp16 gather, fp32 accum):
// bufF[v] = act( dinv[v]*(bufH[v] + sum_{CSR[v]} bufH[u]) + bias )
// quarter-warp per edge: 8 lanes x uint4(8 halves) = one 128B row; 4 edges in flight.
__global__ void __launch_bounds__(256) k_aggh(const float* __restrict__ bias, int do_relu) {
    int w = (blockIdx.x * blockDim.x + threadIdx.x) >> 5;
    if (w >= N_NODES) return;
    int lane = threadIdx.x & 31;
    int q = lane >> 3, sub = lane & 7;
    const uint4* H = (const uint4*)g_bufH;      // row stride = 8 uint4
    float acc[8] = {0.f, 0.f, 0.f, 0.f, 0.f, 0.f, 0.f, 0.f};
    if (q == 0) {                                // self term once
        uint4 v = H[w * 8 + sub];
        const __half2* hp = (const __half2*)&v;
        #pragma unroll
        for (int j = 0; j < 4; j++) {
            float2 f = __half22float2(hp[j]);
            acc[2 * j] += f.x; acc[2 * j + 1] += f.y;
        }
    }
    int beg = g_rowptr[w], end = g_rowptr[w + 1];
    int e = beg + q;
    for (; e + 4 < end; e += 8) {                // unroll 2 per quarter
        int u0 = g_csr[e], u1 = g_csr[e + 4];
        uint4 v0 = H[u0 * 8 + sub];
        uint4 v1 = H[u1 * 8 + sub];
        const __half2* p0 = (const __half2*)&v0;
        const __half2* p1 = (const __half2*)&v1;
        #pragma unroll
        for (int j = 0; j < 4; j++) {
            float2 f0 = __half22float2(p0[j]);
            float2 f1 = __half22float2(p1[j]);
            acc[2 * j]     += f0.x + f1.x;
            acc[2 * j + 1] += f0.y + f1.y;
        }
    }
    for (; e < end; e += 4) {
        int u = g_csr[e];
        uint4 v = H[u * 8 + sub];
        const __half2* p = (const __half2*)&v;
        #pragma unroll
        for (int j = 0; j < 4; j++) {
            float2 f = __half22float2(p[j]);
            acc[2 * j] += f.x; acc[2 * j + 1] += f.y;
        }
    }
    __syncwarp();
    #pragma unroll
    for (int j = 0; j < 8; j++) {
        acc[j] += __shfl_down_sync(0xffffffffu, acc[j], 16);
        acc[j] += __shfl_down_sync(0xffffffffu, acc[j], 8);
    }
    if (q == 0) {
        float s = g_dinv[w];
        float4 bb0 = ((const float4*)bias)[sub * 2];
        float4 bb1 = ((const float4*)bias)[sub * 2 + 1];
        float4 r0, r1;
        r0.x = acc[0] * s + bb0.x; r0.y = acc[1] * s + bb0.y;
        r0.z = acc[2] * s + bb0.z; r0.w = acc[3] * s + bb0.w;
        r1.x = acc[4] * s + bb1.x; r1.y = acc[5] * s + bb1.y;
        r1.z = acc[6] * s + bb1.z; r1.w = acc[7] * s + bb1.w;
        if (do_relu) {
            r0.x = fmaxf(r0.x, 0.f); r0.y = fmaxf(r0.y, 0.f);
            r0.z = fmaxf(r0.z, 0.f); r0.w = fmaxf(r0.w, 0.f);
            r1.x = fmaxf(r1.x, 0.f); r1.y = fmaxf(r1.y, 0.f);
            r1.z = fmaxf(r1.z, 0.f); r1.w = fmaxf(r1.w, 0.f);
        }
        ((float4*)g_bufF)[w * 16 + sub * 2]     = r0;
        ((float4*)g_bufF)[w * 16 + sub * 2 + 1] = r1;
    }
}

// pooling + final linear over bufF; graph ranges via binary search on sorted batch
__global__ void k_pool(const int* __restrict__ batch,
                       const float* __restrict__ Wl, const float* __restrict__ bl,
                       float* __restrict__ outp) {
    __shared__ float sh[256];
    int gph = blockIdx.x;
    int t = threadIdx.x;
    int lo = 0, hi = N_NODES;
    while (lo < hi) { int mid = (lo + hi) >> 1; if (batch[mid] < gph) lo = mid + 1; else hi = mid; }
    int s = lo;
    hi = N_NODES;
    while (lo < hi) { int mid = (lo + hi) >> 1; if (batch[mid] < gph + 1) lo = mid + 1; else hi = mid; }
    int c = lo - s;
    int d = t & 63, grp = t >> 6;
    float acc = 0.f;
    for (int i = grp; i < c; i += 4) acc += g_bufF[(s + i) * HID + d];
    sh[t] = acc;
    __syncthreads();
    if (t < 64) {
        float p = sh[t] + sh[64 + t] + sh[128 + t] + sh[192 + t];
        p *= 1.0f / fmaxf((float)c, 1.0f);
        sh[t] = p;
    }
    __syncthreads();
    if (t < 2) {
        float o = bl[t];
        #pragma unroll 8
        for (int dd = 0; dd < HID; dd++) o += sh[dd] * Wl[dd * 2 + t];
        outp[gph * 2 + t] = o;
    }
}

// ---------------- launch ---------------------------------------------------
extern "C" void kernel_launch(void* const* d_in, const int* in_sizes, int n_in,
                              void* d_out, int out_size) {
    const float* x     = (const float*)d_in[0];
    const int*   ei    = (const int*)d_in[1];    // int64 in reference -> int32 in harness
    const int*   batch = (const int*)d_in[2];
    const float* W1 = (const float*)d_in[3];
    const float* b1 = (const float*)d_in[4];
    const float* W2 = (const float*)d_in[5];
    const float* b2 = (const float*)d_in[6];
    const float* W3 = (const float*)d_in[7];
    const float* b3 = (const float*)d_in[8];
    const float* Wl = (const float*)d_in[9];
    const float* bl = (const float*)d_in[10];
    float* out = (float*)d_out;

    const int TB = 256;
    int nbN = (N_NODES + TB - 1) / TB;                 // 391
    int nbE = (N_EDGES + TB - 1) / TB;                 // 4883
    int nbX = (N_NODES * IN_DIM + TB - 1) / TB;        // 2735
    int nbWarp = (N_NODES + 7) / 8;                    // 12500
    int nbTile = (N_NODES + 63) / 64;                  // 1563

    // CSR build + dinv
    k_zero<<<nbN, TB>>>();
    k_deg<<<nbE, TB>>>(ei);
    k_scan1<<<SCAN_B, 256>>>();
    k_scan3<<<nbN, TB>>>();
    k_scatter<<<nbE, TB>>>(ei);

    // layer 1 (aggregate 7-dim input first)
    k_gx<<<nbX, TB>>>(x);
    k_agg7<<<nbWarp, 256>>>();
    k_h1<<<nbWarp, 256>>>(W1, b1);
    // layer 2
    k_xw64<<<nbTile, 256>>>(W2);
    k_aggh<<<nbWarp, 256>>>(b2, 1);
    // layer 3
    k_xw64<<<nbTile, 256>>>(W3);
    k_aggh<<<nbWarp, 256>>>(b3, 0);

    // pooling + classifier
    k_pool<<<NGRAPH, 256>>>(batch, Wl, bl, out);
}

// round 6
// speedup vs baseline: 1.6977x; 1.6977x over previous
#include <cuda_runtime.h>

#define N_NODES 100000
#define N_EDGES 1250000
#define NGRAPH  256
#define HID     64
#define IN_DIM  7

#define SCAN_E  1024
#define SCAN_B  ((N_NODES + SCAN_E - 1) / SCAN_E)   // 98

// ---------------- scratch (device globals; no allocation allowed) ----------
__device__ float g_dinv[N_NODES];
__device__ int   g_deg[N_NODES];
__device__ int   g_rowptr[N_NODES + 1];
__device__ int   g_cursor[N_NODES];
__device__ int   g_csr[N_EDGES];
__device__ int   g_partials[SCAN_B];
__device__ __align__(16) float g_bufA[N_NODES * HID];
__device__ __align__(16) float g_bufB[N_NODES * HID];
__device__ __align__(16) float g_x7[N_NODES * IN_DIM];

// ---------------- setup kernels -------------------------------------------
__global__ void k_zero() {
    int i = blockIdx.x * blockDim.x + threadIdx.x;
    if (i < N_NODES) g_deg[i] = 0;
}

__global__ void k_deg(const int* __restrict__ ei) {
    int e = blockIdx.x * blockDim.x + threadIdx.x;
    if (e < N_EDGES) atomicAdd(&g_deg[ei[N_EDGES + e]], 1);
}

// exclusive scan of g_deg -> g_rowptr (block-local), raw block sums -> g_partials
__global__ void k_scan1() {
    __shared__ int wraw[8], wscan[8];
    int t = threadIdx.x, b = blockIdx.x;
    int base = b * SCAN_E + t * 4;
    int v0 = 0, v1 = 0, v2 = 0, v3 = 0;
    if (base + 0 < N_NODES) v0 = g_deg[base + 0];
    if (base + 1 < N_NODES) v1 = g_deg[base + 1];
    if (base + 2 < N_NODES) v2 = g_deg[base + 2];
    if (base + 3 < N_NODES) v3 = g_deg[base + 3];
    int ts = v0 + v1 + v2 + v3;
    int lane = t & 31, wid = t >> 5;
    int inc = ts;
    #pragma unroll
    for (int o = 1; o < 32; o <<= 1) {
        int y = __shfl_up_sync(0xffffffffu, inc, o);
        if (lane >= o) inc += y;
    }
    if (lane == 31) wraw[wid] = inc;
    __syncthreads();
    if (t < 8) {
        int w = wraw[t];
        #pragma unroll
        for (int o = 1; o < 8; o <<= 1) {
            int y = __shfl_up_sync(0xffu, w, o);
            if (t >= o) w += y;
        }
        wscan[t] = w;
    }
    __syncthreads();
    int ex = (wid ? wscan[wid - 1] : 0) + (inc - ts);
    if (base + 0 < N_NODES) g_rowptr[base + 0] = ex;  ex += v0;
    if (base + 1 < N_NODES) g_rowptr[base + 1] = ex;  ex += v1;
    if (base + 2 < N_NODES) g_rowptr[base + 2] = ex;  ex += v2;
    if (base + 3 < N_NODES) g_rowptr[base + 3] = ex;
    if (t == 0) g_partials[b] = wscan[7];
}

// finalize rowptr (each block sums its prefix of raw partials), cursor, dinv,
// and scaled 7-dim input gx = x * dinv  (merged k_gx)
__global__ void __launch_bounds__(256) k_scan3(const float* __restrict__ x) {
    __shared__ int sprefix;
    int b = blockIdx.x;
    int p = (b * 256) / SCAN_E;           // number of partials before this block
    if (threadIdx.x < 32) {
        int s = 0;
        for (int j = threadIdx.x; j < p; j += 32) s += g_partials[j];
        #pragma unroll
        for (int o = 16; o; o >>= 1) s += __shfl_down_sync(0xffffffffu, s, o);
        if (threadIdx.x == 0) sprefix = s;
    }
    __syncthreads();
    int i = b * 256 + threadIdx.x;
    if (i < N_NODES) {
        int r = g_rowptr[i] + sprefix;
        g_rowptr[i] = r;
        g_cursor[i] = r;
        float dv = rsqrtf((float)(g_deg[i] + 1));   // +1 self-loop
        g_dinv[i] = dv;
        #pragma unroll
        for (int j = 0; j < IN_DIM; j++)
            g_x7[i * IN_DIM + j] = x[i * IN_DIM + j] * dv;
    }
    if (b == 0 && threadIdx.x == 0) g_rowptr[N_NODES] = N_EDGES;
}

__global__ void k_scatter(const int* __restrict__ ei) {
    int e = blockIdx.x * blockDim.x + threadIdx.x;
    if (e < N_EDGES) {
        int d = ei[N_EDGES + e];
        int p = atomicAdd(&g_cursor[d], 1);
        g_csr[p] = ei[e];
    }
}

// ---------------- layer 1: fused 7-dim aggregate + 7->64 GEMM + relu -------
// warp per node: a7 = dinv*(gx[v] + sum gx[u]);  H1 = relu(a7 @ W1 + b1) -> bufB
__global__ void __launch_bounds__(256) k_l1(const float* __restrict__ W1,
                                            const float* __restrict__ b1) {
    __shared__ float sW[IN_DIM * HID];
    __shared__ float sB[HID];
    int t = threadIdx.x;
    for (int i = t; i < IN_DIM * HID; i += 256) sW[i] = W1[i];
    if (t < HID) sB[t] = b1[t];
    __syncthreads();
    int w = blockIdx.x * 8 + (t >> 5);
    if (w >= N_NODES) return;
    int lane = t & 31;
    int grp = lane / IN_DIM, dim = lane - grp * IN_DIM;  // grp 0..3 active
    float acc = 0.f;
    if (grp == 0) acc = g_x7[w * IN_DIM + dim];          // self term
    if (grp < 4) {
        int beg = g_rowptr[w], end = g_rowptr[w + 1];
        for (int e = beg + grp; e < end; e += 4)
            acc += g_x7[g_csr[e] * IN_DIM + dim];
    }
    __syncwarp();
    acc += __shfl_down_sync(0xffffffffu, acc, 14);
    acc += __shfl_down_sync(0xffffffffu, acc, 7);
    float a7 = acc * g_dinv[w];                          // valid in lanes 0..6
    float a0 = sB[lane], a1 = sB[32 + lane];
    #pragma unroll
    for (int k = 0; k < IN_DIM; k++) {
        float xk = __shfl_sync(0xffffffffu, a7, k);
        a0 += xk * sW[k * HID + lane];
        a1 += xk * sW[k * HID + 32 + lane];
    }
    g_bufB[w * HID + lane]      = fmaxf(a0, 0.f);
    g_bufB[w * HID + 32 + lane] = fmaxf(a1, 0.f);
}

// ---------------- 64-dim layers --------------------------------------------
// GEMM tile: bufA = dinv[v] * (bufB[v] @ W); 64 nodes/block, 128 threads,
// 8x4 register blocking -> 3 LDS.128 per 32 FFMA (FFMA-bound).
__global__ void __launch_bounds__(128) k_xw64(const float* __restrict__ W) {
    __shared__ __align__(16) float sA[64][68];  // sA[k][m]
    __shared__ __align__(16) float sW[64][68];  // sW[k][n]
    int t = threadIdx.x;
    int nb = blockIdx.x * 64;
    const float4* W4 = (const float4*)W;
    #pragma unroll
    for (int i = t; i < 1024; i += 128) {
        float4 v = W4[i];
        int k = i >> 4, n4 = i & 15;
        *(float4*)&sW[k][n4 * 4] = v;
    }
    const float4* B4 = (const float4*)g_bufB;
    #pragma unroll
    for (int i = t; i < 1024; i += 128) {
        int m = i >> 4, k4 = i & 15;
        int node = nb + m;
        float4 v = (node < N_NODES) ? B4[node * 16 + k4] : make_float4(0.f, 0.f, 0.f, 0.f);
        sA[k4 * 4 + 0][m] = v.x;
        sA[k4 * 4 + 1][m] = v.y;
        sA[k4 * 4 + 2][m] = v.z;
        sA[k4 * 4 + 3][m] = v.w;
    }
    __syncthreads();
    int tx = t & 15, ty = t >> 4;       // tx: dim quad, ty: 8-node group
    float acc[8][4] = {};
    #pragma unroll
    for (int k = 0; k < 64; k++) {
        float4 wv = *(const float4*)&sW[k][tx * 4];
        float4 x0 = *(const float4*)&sA[k][ty * 8];
        float4 x1 = *(const float4*)&sA[k][ty * 8 + 4];
        float a[8] = {x0.x, x0.y, x0.z, x0.w, x1.x, x1.y, x1.z, x1.w};
        #pragma unroll
        for (int m = 0; m < 8; m++) {
            acc[m][0] += a[m] * wv.x; acc[m][1] += a[m] * wv.y;
            acc[m][2] += a[m] * wv.z; acc[m][3] += a[m] * wv.w;
        }
    }
    #pragma unroll
    for (int m = 0; m < 8; m++) {
        int node = nb + ty * 8 + m;
        if (node < N_NODES) {
            float s = g_dinv[node];
            float4 r = make_float4(acc[m][0] * s, acc[m][1] * s,
                                   acc[m][2] * s, acc[m][3] * s);
            *(float4*)&g_bufA[node * HID + tx * 4] = r;
        }
    }
}

// aggregation: bufB[v] = act( dinv[v]*(bufA[v] + sum gather) + bias )
// half-warp float4; halves split edges; unroll 4 for MLP.
__global__ void __launch_bounds__(256) k_agg(const float* __restrict__ bias, int do_relu) {
    int w = (blockIdx.x * blockDim.x + threadIdx.x) >> 5;
    if (w >= N_NODES) return;
    int lane = threadIdx.x & 31;
    int half = lane >> 4, sub = lane & 15;
    const float4* inA = (const float4*)g_bufA;
    float4 acc;
    if (half == 0) acc = inA[w * 16 + sub];               // self term once
    else           acc = make_float4(0.f, 0.f, 0.f, 0.f);
    int beg = g_rowptr[w], end = g_rowptr[w + 1];
    int e = beg + half;
    for (; e + 6 < end; e += 8) {                          // 4 edges per half in flight
        int u0 = g_csr[e],     u1 = g_csr[e + 2];
        int u2 = g_csr[e + 4], u3 = g_csr[e + 6];
        float4 b0 = inA[u0 * 16 + sub];
        float4 b1 = inA[u1 * 16 + sub];
        float4 b2 = inA[u2 * 16 + sub];
        float4 b3 = inA[u3 * 16 + sub];
        acc.x += (b0.x + b1.x) + (b2.x + b3.x);
        acc.y += (b0.y + b1.y) + (b2.y + b3.y);
        acc.z += (b0.z + b1.z) + (b2.z + b3.z);
        acc.w += (b0.w + b1.w) + (b2.w + b3.w);
    }
    for (; e < end; e += 2) {
        int u = g_csr[e];
        float4 b = inA[u * 16 + sub];
        acc.x += b.x; acc.y += b.y; acc.z += b.z; acc.w += b.w;
    }
    __syncwarp();
    acc.x += __shfl_down_sync(0xffffffffu, acc.x, 16);
    acc.y += __shfl_down_sync(0xffffffffu, acc.y, 16);
    acc.z += __shfl_down_sync(0xffffffffu, acc.z, 16);
    acc.w += __shfl_down_sync(0xffffffffu, acc.w, 16);
    if (half == 0) {
        float s = g_dinv[w];
        float4 bb = ((const float4*)bias)[sub];
        float4 r;
        r.x = acc.x * s + bb.x; r.y = acc.y * s + bb.y;
        r.z = acc.z * s + bb.z; r.w = acc.w * s + bb.w;
        if (do_relu) {
            r.x = fmaxf(r.x, 0.f); r.y = fmaxf(r.y, 0.f);
            r.z = fmaxf(r.z, 0.f); r.w = fmaxf(r.w, 0.f);
        }
        ((float4*)g_bufB)[w * 16 + sub] = r;
    }
}

// pooling + final linear over bufB; graph ranges via binary search on sorted batch
__global__ void k_pool(const int* __restrict__ batch,
                       const float* __restrict__ Wl, const float* __restrict__ bl,
                       float* __restrict__ outp) {
    __shared__ float sh[256];
    int gph = blockIdx.x;
    int t = threadIdx.x;
    int lo = 0, hi = N_NODES;
    while (lo < hi) { int mid = (lo + hi) >> 1; if (batch[mid] < gph) lo = mid + 1; else hi = mid; }
    int s = lo;
    hi = N_NODES;
    while (lo < hi) { int mid = (lo + hi) >> 1; if (batch[mid] < gph + 1) lo = mid + 1; else hi = mid; }
    int c = lo - s;
    int d = t & 63, grp = t >> 6;
    float acc = 0.f;
    for (int i = grp; i < c; i += 4) acc += g_bufB[(s + i) * HID + d];
    sh[t] = acc;
    __syncthreads();
    if (t < 64) {
        float p = sh[t] + sh[64 + t] + sh[128 + t] + sh[192 + t];
        p *= 1.0f / fmaxf((float)c, 1.0f);
        sh[t] = p;
    }
    __syncthreads();
    if (t < 2) {
        float o = bl[t];
        #pragma unroll 8
        for (int dd = 0; dd < HID; dd++) o += sh[dd] * Wl[dd * 2 + t];
        outp[gph * 2 + t] = o;
    }
}

// ---------------- launch ---------------------------------------------------
extern "C" void kernel_launch(void* const* d_in, const int* in_sizes, int n_in,
                              void* d_out, int out_size) {
    const float* x     = (const float*)d_in[0];
    const int*   ei    = (const int*)d_in[1];    // int64 in reference -> int32 in harness
    const int*   batch = (const int*)d_in[2];
    const float* W1 = (const float*)d_in[3];
    const float* b1 = (const float*)d_in[4];
    const float* W2 = (const float*)d_in[5];
    const float* b2 = (const float*)d_in[6];
    const float* W3 = (const float*)d_in[7];
    const float* b3 = (const float*)d_in[8];
    const float* Wl = (const float*)d_in[9];
    const float* bl = (const float*)d_in[10];
    float* out = (float*)d_out;

    const int TB = 256;
    int nbN = (N_NODES + TB - 1) / TB;                 // 391
    int nbE = (N_EDGES + TB - 1) / TB;                 // 4883
    int nbWarp = (N_NODES + 7) / 8;                    // 12500
    int nbTile = (N_NODES + 63) / 64;                  // 1563

    // CSR build + dinv + scaled input
    k_zero<<<nbN, TB>>>();
    k_deg<<<nbE, TB>>>(ei);
    k_scan1<<<SCAN_B, 256>>>();
    k_scan3<<<nbN, TB>>>(x);
    k_scatter<<<nbE, TB>>>(ei);

    // layer 1 (fused 7-dim aggregate + GEMM + relu)
    k_l1<<<nbWarp, 256>>>(W1, b1);
    // layer 2
    k_xw64<<<nbTile, 128>>>(W2);
    k_agg<<<nbWarp, 256>>>(b2, 1);
    // layer 3
    k_xw64<<<nbTile, 128>>>(W3);
    k_agg<<<nbWarp, 256>>>(b3, 0);

    // pooling + classifier
    k_pool<<<NGRAPH, 256>>>(batch, Wl, bl, out);
}